// round 5
// baseline (speedup 1.0000x reference)
#include <cuda_runtime.h>
#include <cstdint>

// Problem constants (fixed by setup_inputs)
#define LDIM 2048
#define DDIM 4096
#define KEXP 8
#define MPOS 1024
#define UPOS 1024
#define DPROJ 512
#define HHID 2048
#define EHDIM 16384   // KEXP * HHID

// ---------------------------------------------------------------------------
// Device-global scratch (no runtime allocation allowed)
// ---------------------------------------------------------------------------
__device__ float    g_A[(size_t)UPOS * EHDIM];    // anchors @ W1_top
__device__ float    g_B[(size_t)MPOS * EHDIM];    // masks   @ W1_bot
__device__ uint32_t g_G[(size_t)MPOS * EHDIM];    // tf32 bits of gated/combined gelu
__device__ uint32_t g_hM[(size_t)MPOS * DDIM];    // tf32 gathered mask rows of h
__device__ uint32_t g_hU[(size_t)UPOS * DDIM];    // tf32 gathered anchor rows of h
__device__ float    g_q[MPOS * DPROJ];
__device__ float    g_k[UPOS * DPROJ];
__device__ float    g_gate[MPOS * KEXP];
__device__ float    g_cmb[MPOS * 10];
// Pre-converted tf32 weights
__device__ uint32_t g_W1c[(size_t)KEXP * 2 * DDIM * HHID];  // 512MB
__device__ uint32_t g_W2c[(size_t)EHDIM * DDIM];            // 256MB
__device__ uint32_t g_Wqc[(size_t)DDIM * DPROJ];
__device__ uint32_t g_Wkc[(size_t)DDIM * DPROJ];

// ---------------------------------------------------------------------------
// helpers
// ---------------------------------------------------------------------------
__device__ __forceinline__ uint32_t f2tf(float x) {
    uint32_t r;
    asm("cvt.rna.tf32.f32 %0, %1;" : "=r"(r) : "f"(x));
    return r;
}
__device__ __forceinline__ uint32_t smem_u32(const void* p) {
    uint32_t a;
    asm("{ .reg .u64 t; cvta.to.shared.u64 t, %1; cvt.u32.u64 %0, t; }" : "=r"(a) : "l"(p));
    return a;
}
__device__ __forceinline__ void cp16(uint32_t dst, const void* src) {
    asm volatile("cp.async.cg.shared.global [%0], [%1], 16;" :: "r"(dst), "l"(src));
}
#define CP_COMMIT() asm volatile("cp.async.commit_group;" ::: "memory")
#define CP_WAIT(n)  asm volatile("cp.async.wait_group %0;" :: "n"(n) : "memory")

__device__ __forceinline__ void mma_tf32(float* c, const uint32_t* a, const uint32_t* b) {
    asm volatile(
        "mma.sync.aligned.m16n8k8.row.col.f32.tf32.tf32.f32 "
        "{%0,%1,%2,%3}, {%4,%5,%6,%7}, {%8,%9}, {%0,%1,%2,%3};\n"
        : "+f"(c[0]), "+f"(c[1]), "+f"(c[2]), "+f"(c[3])
        : "r"(a[0]), "r"(a[1]), "r"(a[2]), "r"(a[3]), "r"(b[0]), "r"(b[1]));
}

// smem stage layout (bytes):
//   A tile: [128 m][36 words]  rows 144 B  (banks 4g+tg  -> conflict-free)
//   B tile: [32 k][264 words]  rows 1056 B (264 mod 32 = 8 -> banks 8tg+g, CF)
#define ALD 36
#define BLD 264
#define A_BYTES (128 * ALD * 4)          // 18432
#define B_BYTES (32 * BLD * 4)           // 33792
#define SM_STAGE (A_BYTES + B_BYTES)     // 52224
#define SM_TOTAL (3 * SM_STAGE)          // 156672

// ---------------------------------------------------------------------------
// tf32 GEMM, cp.async 3-stage pipeline.
// C[m, n] = sum_k A(m)[k] * W(k, n) ;  all operands pre-converted tf32 bits.
// BM=128, BN=256, BK=32; 256 threads; 8 warps (2m x 4n), warp tile 64x64.
// grid = (M/128, N/256 [, 2]); blockIdx.z==1 selects (Ag2, Wg2, Cg2).
// ---------------------------------------------------------------------------
__global__ __launch_bounds__(256, 1)
void gemm_cp(const uint32_t* __restrict__ Ag, int lda,
             const uint32_t* __restrict__ Wg, int ldw, int cpe, size_t estride,
             float* __restrict__ Cg, int ldc, const int* __restrict__ rowC,
             int Kdim,
             const uint32_t* __restrict__ Ag2, const uint32_t* __restrict__ Wg2,
             float* __restrict__ Cg2)
{
    extern __shared__ char smc[];

    if (blockIdx.z) { Ag = Ag2; Wg = Wg2; Cg = Cg2; }

    const int tid = threadIdx.x, lane = tid & 31, wid = tid >> 5;
    const int m0 = blockIdx.x * 128, n0 = blockIdx.y * 256;
    const uint32_t sb = smem_u32(smc);
    const uint32_t* wbase = Wg + (size_t)(n0 / cpe) * estride + (size_t)(n0 % cpe);

    const int wm = (wid & 1) * 64, wn = (wid >> 1) * 64;
    const int g = lane >> 2, tg = lane & 3;

    // A loader: rows ar+32i (i<4), 16B chunk akq
    const int ar = tid >> 3, akq = tid & 7;
    const uint32_t* aptr[4];
#pragma unroll
    for (int i = 0; i < 4; i++)
        aptr[i] = Ag + (size_t)(m0 + ar + 32 * i) * lda + akq * 4;
    // B loader: k rows bk4+4i (i<8), 16B chunk bnq (0..63)
    const int bk4 = tid >> 6, bnq = tid & 63;
    const uint32_t* bbase = wbase + (size_t)bk4 * ldw + bnq * 4;

#define ISSUE(s, kt)                                                             \
    {                                                                            \
        uint32_t ab = sb + (s) * SM_STAGE;                                       \
        _Pragma("unroll")                                                        \
        for (int i = 0; i < 4; i++)                                              \
            cp16(ab + (ar + 32 * i) * (ALD * 4) + akq * 16, aptr[i] + (kt));     \
        uint32_t bb = sb + (s) * SM_STAGE + A_BYTES;                             \
        _Pragma("unroll")                                                        \
        for (int i = 0; i < 8; i++)                                              \
            cp16(bb + (bk4 + 4 * i) * (BLD * 4) + bnq * 16,                      \
                 bbase + (size_t)((kt) + 4 * i) * ldw);                          \
        CP_COMMIT();                                                             \
    }

    float acc[4][8][4];
#pragma unroll
    for (int i = 0; i < 4; i++)
#pragma unroll
        for (int j = 0; j < 8; j++)
#pragma unroll
            for (int c = 0; c < 4; c++) acc[i][j][c] = 0.f;

    const int KT = Kdim / 32;
    ISSUE(0, 0);
    ISSUE(1, 32);

    for (int ki = 0; ki < KT; ki++) {
        if (ki == KT - 1) { CP_WAIT(0); } else { CP_WAIT(1); }
        __syncthreads();
        if (ki + 2 < KT) ISSUE((ki + 2) % 3, (ki + 2) * 32);

        const uint32_t* As = (const uint32_t*)(smc + (ki % 3) * SM_STAGE);
        const uint32_t* Bs = (const uint32_t*)(smc + (ki % 3) * SM_STAGE + A_BYTES);
#pragma unroll
        for (int ks = 0; ks < 4; ks++) {
            const int kb = ks * 8;
            uint32_t a[4][4], b[8][2];
#pragma unroll
            for (int mf = 0; mf < 4; mf++) {
                int r = wm + mf * 16 + g;
                a[mf][0] = As[r * ALD + kb + tg];
                a[mf][1] = As[(r + 8) * ALD + kb + tg];
                a[mf][2] = As[r * ALD + kb + tg + 4];
                a[mf][3] = As[(r + 8) * ALD + kb + tg + 4];
            }
#pragma unroll
            for (int nf = 0; nf < 8; nf++) {
                int c = wn + nf * 8 + g;
                b[nf][0] = Bs[(kb + tg) * BLD + c];
                b[nf][1] = Bs[(kb + tg + 4) * BLD + c];
            }
#pragma unroll
            for (int mf = 0; mf < 4; mf++)
#pragma unroll
                for (int nf = 0; nf < 8; nf++)
                    mma_tf32(acc[mf][nf], a[mf], b[nf]);
        }
    }

#pragma unroll
    for (int mf = 0; mf < 4; mf++) {
        int r0 = m0 + wm + mf * 16 + g;
        int r1 = r0 + 8;
        size_t o0 = (size_t)(rowC ? rowC[r0] : r0) * (size_t)ldc;
        size_t o1 = (size_t)(rowC ? rowC[r1] : r1) * (size_t)ldc;
#pragma unroll
        for (int nf = 0; nf < 8; nf++) {
            int c = n0 + wn + nf * 8 + tg * 2;
            *reinterpret_cast<float2*>(Cg + o0 + c) = make_float2(acc[mf][nf][0], acc[mf][nf][1]);
            *reinterpret_cast<float2*>(Cg + o1 + c) = make_float2(acc[mf][nf][2], acc[mf][nf][3]);
        }
    }
#undef ISSUE
}

// ---------------------------------------------------------------------------
// Elementwise fp32 -> tf32-bits convert (vectorized, grid-stride)
// ---------------------------------------------------------------------------
__global__ void conv_tf32(const float* __restrict__ s, uint32_t* __restrict__ d,
                          size_t n4)
{
    size_t i = (size_t)blockIdx.x * blockDim.x + threadIdx.x;
    size_t stride = (size_t)gridDim.x * blockDim.x;
    for (; i < n4; i += stride) {
        float4 v = reinterpret_cast<const float4*>(s)[i];
        uint4 o;
        o.x = f2tf(v.x); o.y = f2tf(v.y); o.z = f2tf(v.z); o.w = f2tf(v.w);
        reinterpret_cast<uint4*>(d)[i] = o;
    }
}

// gather h rows by index + convert to tf32 bits
__global__ void gather_tf32(const float* __restrict__ h, const int* __restrict__ idx,
                            uint32_t* __restrict__ dst)
{
    const int r = blockIdx.x;
    const float4* s = reinterpret_cast<const float4*>(h + (size_t)idx[r] * DDIM);
    uint4* d = reinterpret_cast<uint4*>(dst + (size_t)r * DDIM);
    for (int i = threadIdx.x; i < DDIM / 4; i += 256) {
        float4 v = s[i];
        uint4 o;
        o.x = f2tf(v.x); o.y = f2tf(v.y); o.z = f2tf(v.z); o.w = f2tf(v.w);
        d[i] = o;
    }
}

// ---------------------------------------------------------------------------
// gate[m, :] = softmax(h[midx[m]] @ Wr + br)
// ---------------------------------------------------------------------------
__global__ void gate_kernel(const float* __restrict__ h, const int* __restrict__ midx,
                            const float* __restrict__ Wr, const float* __restrict__ br,
                            float* __restrict__ gate)
{
    const int m = blockIdx.x;
    const int tid = threadIdx.x;
    const float* hp = h + (size_t)midx[m] * DDIM;

    float acc[KEXP];
#pragma unroll
    for (int e = 0; e < KEXP; e++) acc[e] = 0.f;
    for (int d = tid; d < DDIM; d += 256) {
        float hv = hp[d];
        const float4* wr = reinterpret_cast<const float4*>(Wr + (size_t)d * KEXP);
        float4 w0 = wr[0], w1 = wr[1];
        acc[0] += hv * w0.x; acc[1] += hv * w0.y; acc[2] += hv * w0.z; acc[3] += hv * w0.w;
        acc[4] += hv * w1.x; acc[5] += hv * w1.y; acc[6] += hv * w1.z; acc[7] += hv * w1.w;
    }
#pragma unroll
    for (int off = 16; off > 0; off >>= 1)
#pragma unroll
        for (int e = 0; e < KEXP; e++)
            acc[e] += __shfl_down_sync(0xffffffffu, acc[e], off);

    __shared__ float ws[8][KEXP];
    const int w = tid >> 5, lane = tid & 31;
    if (lane == 0)
#pragma unroll
        for (int e = 0; e < KEXP; e++) ws[w][e] = acc[e];
    __syncthreads();
    if (tid == 0) {
        float l[KEXP];
#pragma unroll
        for (int e = 0; e < KEXP; e++) {
            float s = br[e];
#pragma unroll
            for (int ww = 0; ww < 8; ww++) s += ws[ww][e];
            l[e] = s;
        }
        float mx = l[0];
#pragma unroll
        for (int e = 1; e < KEXP; e++) mx = fmaxf(mx, l[e]);
        float sum = 0.f;
#pragma unroll
        for (int e = 0; e < KEXP; e++) { l[e] = expf(l[e] - mx); sum += l[e]; }
        float inv = 1.f / sum;
#pragma unroll
        for (int e = 0; e < KEXP; e++) gate[m * KEXP + e] = l[e] * inv;
    }
}

// ---------------------------------------------------------------------------
// per-mask pair scores + segment softmax (anchors u = m-5 .. m+4 in [0,UPOS))
// ---------------------------------------------------------------------------
__global__ void score_combine(const float* __restrict__ q, const float* __restrict__ k,
                              const float* __restrict__ bq, const float* __restrict__ bk,
                              float* __restrict__ cmb)
{
    const int m = blockIdx.x;
    const int w = threadIdx.x >> 5;    // 0..9
    const int lane = threadIdx.x & 31;
    const int u = m - 5 + w;
    const bool valid = (u >= 0) && (u < UPOS);

    __shared__ float sc[10];
    float s = 0.f;
    if (valid) {
        const float* qp = q + (size_t)m * DPROJ;
        const float* kp = k + (size_t)u * DPROJ;
        for (int i = lane; i < DPROJ; i += 32)
            s += (qp[i] + bq[i]) * (kp[i] + bk[i]);
#pragma unroll
        for (int off = 16; off > 0; off >>= 1)
            s += __shfl_down_sync(0xffffffffu, s, off);
    }
    if (lane == 0) sc[w] = valid ? s * 0.044194173824159216f : -1e30f;
    __syncthreads();
    if (threadIdx.x == 0) {
        float mx = -1e30f;
#pragma unroll
        for (int j = 0; j < 10; j++) mx = fmaxf(mx, sc[j]);
        float e[10]; float sum = 0.f;
#pragma unroll
        for (int j = 0; j < 10; j++) {
            e[j] = (sc[j] > -1e29f) ? expf(sc[j] - mx) : 0.f;
            sum += e[j];
        }
        float inv = 1.f / fmaxf(sum, 1e-8f);
#pragma unroll
        for (int j = 0; j < 10; j++) cmb[m * 10 + j] = e[j] * inv;
    }
}

// ---------------------------------------------------------------------------
// g_G[m, n] = tf32( gate[m][n/H] * sum_j cmb[m][j] * gelu(A[u_j,n]+B[m,n]+b1[n]) )
// ---------------------------------------------------------------------------
__global__ void aggregate_kernel(const float* __restrict__ A, const float* __restrict__ B,
                                 const float* __restrict__ b1, const float* __restrict__ cmb,
                                 const float* __restrict__ gate, uint32_t* __restrict__ G)
{
    const int m = blockIdx.y;
    const int n = blockIdx.x * 256 + threadIdx.x;
    __shared__ float c[10];
    __shared__ int   us[10];
    __shared__ float gt[KEXP];
    if (threadIdx.x < 10) {
        c[threadIdx.x] = cmb[m * 10 + threadIdx.x];
        int u = m - 5 + threadIdx.x;
        us[threadIdx.x] = min(max(u, 0), UPOS - 1);
    }
    if (threadIdx.x < KEXP) gt[threadIdx.x] = gate[m * KEXP + threadIdx.x];
    __syncthreads();

    const float Bv = B[(size_t)m * EHDIM + n] + b1[n];
    float acc = 0.f;
#pragma unroll
    for (int j = 0; j < 10; j++) {
        float x = A[(size_t)us[j] * EHDIM + n] + Bv;
        float ge = 0.5f * x * (1.f + erff(x * 0.70710678118654752f));
        acc = fmaf(c[j], ge, acc);
    }
    G[(size_t)m * EHDIM + n] = f2tf(gt[n >> 11] * acc);
}

// out[midx[m], d] += sum_e gate[m][e] * b2[e][d]
__global__ void addb2_kernel(const float* __restrict__ gate, const float* __restrict__ b2,
                             const int* __restrict__ midx, float* __restrict__ out)
{
    const int m = blockIdx.y;
    const int d = blockIdx.x * 256 + threadIdx.x;
    float s = 0.f;
#pragma unroll
    for (int e = 0; e < KEXP; e++)
        s = fmaf(gate[m * KEXP + e], b2[(size_t)e * DDIM + d], s);
    out[(size_t)midx[m] * DDIM + d] += s;
}

// ---------------------------------------------------------------------------
extern "C" void kernel_launch(void* const* d_in, const int* in_sizes, int n_in,
                              void* d_out, int out_size)
{
    const float* h   = (const float*)d_in[0];
    const int*   midx= (const int*)d_in[1];
    const int*   uidx= (const int*)d_in[2];
    const float* Wr  = (const float*)d_in[4];
    const float* br  = (const float*)d_in[5];
    const float* W1  = (const float*)d_in[6];
    const float* b1  = (const float*)d_in[7];
    const float* W2  = (const float*)d_in[8];
    const float* b2  = (const float*)d_in[9];
    const float* Wq  = (const float*)d_in[10];
    const float* bq  = (const float*)d_in[11];
    const float* Wk  = (const float*)d_in[12];
    const float* bk  = (const float*)d_in[13];
    float* out = (float*)d_out;

    float *pA, *pB, *pq, *pk, *pgate, *pcmb;
    uint32_t *pG, *phM, *phU, *pW1c, *pW2c, *pWqc, *pWkc;
    cudaGetSymbolAddress((void**)&pA, g_A);
    cudaGetSymbolAddress((void**)&pB, g_B);
    cudaGetSymbolAddress((void**)&pG, g_G);
    cudaGetSymbolAddress((void**)&phM, g_hM);
    cudaGetSymbolAddress((void**)&phU, g_hU);
    cudaGetSymbolAddress((void**)&pq, g_q);
    cudaGetSymbolAddress((void**)&pk, g_k);
    cudaGetSymbolAddress((void**)&pgate, g_gate);
    cudaGetSymbolAddress((void**)&pcmb, g_cmb);
    cudaGetSymbolAddress((void**)&pW1c, g_W1c);
    cudaGetSymbolAddress((void**)&pW2c, g_W2c);
    cudaGetSymbolAddress((void**)&pWqc, g_Wqc);
    cudaGetSymbolAddress((void**)&pWkc, g_Wkc);

    cudaFuncSetAttribute(gemm_cp, cudaFuncAttributeMaxDynamicSharedMemorySize, SM_TOTAL);

    // zero output (odd rows stay zero; even rows overwritten by final GEMM)
    cudaMemsetAsync(out, 0, (size_t)out_size * sizeof(float));

    // pre-convert weights to tf32 bits (RNA)
    conv_tf32<<<8192, 256>>>(W1, pW1c, (size_t)KEXP * 2 * DDIM * HHID / 4);
    conv_tf32<<<4096, 256>>>(W2, pW2c, (size_t)EHDIM * DDIM / 4);
    conv_tf32<<<1024, 256>>>(Wq, pWqc, (size_t)DDIM * DPROJ / 4);
    conv_tf32<<<1024, 256>>>(Wk, pWkc, (size_t)DDIM * DPROJ / 4);

    // gather + convert h rows
    gather_tf32<<<MPOS, 256>>>(h, midx, phM);
    gather_tf32<<<UPOS, 256>>>(h, uidx, phU);

    // gate (fp32)
    gate_kernel<<<MPOS, 256>>>(h, midx, Wr, br, pgate);

    // q = hM @ Wq ; k = hU @ Wk  (batched via blockIdx.z)
    gemm_cp<<<dim3(MPOS / 128, DPROJ / 256, 2), 256, SM_TOTAL>>>(
        phM, DDIM, pWqc, DPROJ, DPROJ, 0, pq, DPROJ, nullptr, DDIM,
        phU, pWkc, pk);

    // per-mask segment softmax over <=10 anchors
    score_combine<<<MPOS, 320>>>(pq, pk, bq, bk, pcmb);

    // A = hU @ W1_top ; B = hM @ W1_bot   (expert-strided columns, cpe=HHID)
    gemm_cp<<<dim3(UPOS / 128, EHDIM / 256, 1), 256, SM_TOTAL>>>(
        phU, DDIM, pW1c, HHID, HHID, (size_t)2 * DDIM * HHID, pA, EHDIM, nullptr, DDIM,
        nullptr, nullptr, nullptr);
    gemm_cp<<<dim3(MPOS / 128, EHDIM / 256, 1), 256, SM_TOTAL>>>(
        phM, DDIM, pW1c + (size_t)DDIM * HHID, HHID, HHID, (size_t)2 * DDIM * HHID,
        pB, EHDIM, nullptr, DDIM,
        nullptr, nullptr, nullptr);

    // gelu + combine aggregation, gate folded in, tf32 output
    aggregate_kernel<<<dim3(EHDIM / 256, MPOS), 256>>>(pA, pB, b1, pcmb, pgate, pG);

    // out[masks] = G @ W2_flat   (K = 16384, W2 flat contiguous [16384 x 4096])
    gemm_cp<<<dim3(MPOS / 128, DDIM / 256, 1), 256, SM_TOTAL>>>(
        pG, EHDIM, pW2c, DDIM, DDIM, 0, out, DDIM, midx, EHDIM,
        nullptr, nullptr, nullptr);

    // + sum_e gate*b2 (combine weights sum to 1 per mask)
    addb2_kernel<<<dim3(DDIM / 256, MPOS), 256>>>(pgate, b2, midx, out);
}

// round 6
// speedup vs baseline: 1.1089x; 1.1089x over previous
#include <cuda_runtime.h>
#include <cstdint>

// Problem constants (fixed by setup_inputs)
#define LDIM 2048
#define DDIM 4096
#define KEXP 8
#define MPOS 1024
#define UPOS 1024
#define DPROJ 512
#define HHID 2048
#define EHDIM 16384   // KEXP * HHID

// ---------------------------------------------------------------------------
// Device-global scratch (no runtime allocation allowed)
// ---------------------------------------------------------------------------
__device__ float    g_A[(size_t)UPOS * EHDIM];    // anchors @ W1_top
__device__ float    g_B[(size_t)MPOS * EHDIM];    // masks   @ W1_bot
__device__ uint32_t g_G[(size_t)MPOS * EHDIM];    // tf32 bits of gated/combined gelu
__device__ uint32_t g_hM[(size_t)MPOS * DDIM];    // tf32 gathered mask rows of h
__device__ uint32_t g_hU[(size_t)UPOS * DDIM];    // tf32 gathered anchor rows of h
__device__ float    g_q[MPOS * DPROJ];
__device__ float    g_k[UPOS * DPROJ];
__device__ float    g_gate[MPOS * KEXP];
__device__ float    g_cmb[MPOS * 10];

// ---------------------------------------------------------------------------
// helpers
// ---------------------------------------------------------------------------
__device__ __forceinline__ uint32_t f2tf(float x) {
    uint32_t r;
    asm("cvt.rna.tf32.f32 %0, %1;" : "=r"(r) : "f"(x));
    return r;
}
__device__ __forceinline__ uint32_t smem_u32(const void* p) {
    uint32_t a;
    asm("{ .reg .u64 t; cvta.to.shared.u64 t, %1; cvt.u32.u64 %0, t; }" : "=r"(a) : "l"(p));
    return a;
}
__device__ __forceinline__ void cp16(uint32_t dst, const void* src) {
    asm volatile("cp.async.cg.shared.global [%0], [%1], 16;" :: "r"(dst), "l"(src));
}
#define CP_COMMIT() asm volatile("cp.async.commit_group;" ::: "memory")
#define CP_WAIT(n)  asm volatile("cp.async.wait_group %0;" :: "n"(n) : "memory")

__device__ __forceinline__ void mma_tf32(float* c, const uint32_t* a, const uint32_t* b) {
    asm volatile(
        "mma.sync.aligned.m16n8k8.row.col.f32.tf32.tf32.f32 "
        "{%0,%1,%2,%3}, {%4,%5,%6,%7}, {%8,%9}, {%0,%1,%2,%3};\n"
        : "+f"(c[0]), "+f"(c[1]), "+f"(c[2]), "+f"(c[3])
        : "r"(a[0]), "r"(a[1]), "r"(a[2]), "r"(a[3]), "r"(b[0]), "r"(b[1]));
}

// smem stage layout (bytes):
//   A tile: [128 m][36 words]  rows 144 B (banks 4g+tg -> conflict-free)
//   B tile: [32 k][136 words]  rows 544 B (136 mod 32 = 8 -> banks 8tg+g, CF)
#define ALD 36
#define BLD 136
#define A_BYTES (128 * ALD * 4)          // 18432
#define B_BYTES (32 * BLD * 4)           // 17408
#define SM_STAGE (A_BYTES + B_BYTES)     // 35840
#define SM_TOTAL (3 * SM_STAGE)          // 107520

// ---------------------------------------------------------------------------
// tf32 GEMM, cp.async 3-stage pipeline.
// C[m, n] = sum_k A(m)[k] * W(k, n)
//   A operand: pre-converted tf32 bits.
//   W operand: RAW fp32, converted to tf32 (RNA) at fragment-load time.
// BM=BN=128, BK=32, 256 threads, 8 warps each 64x32 via m16n8k8.
// grid = (M/128, N/128 [, 2]); blockIdx.z==1 selects (Ag2, Wg2, Cg2).
// ---------------------------------------------------------------------------
__global__ __launch_bounds__(256, 2)
void gemm_cp(const uint32_t* __restrict__ Ag, int lda,
             const float* __restrict__ Wg, int ldw, int cpe, size_t estride,
             float* __restrict__ Cg, int ldc, const int* __restrict__ rowC,
             int Kdim,
             const uint32_t* __restrict__ Ag2, const float* __restrict__ Wg2,
             float* __restrict__ Cg2)
{
    extern __shared__ char smc[];

    if (blockIdx.z) { Ag = Ag2; Wg = Wg2; Cg = Cg2; }

    const int tid = threadIdx.x, lane = tid & 31, wid = tid >> 5;
    const int m0 = blockIdx.x * 128, n0 = blockIdx.y * 128;
    const uint32_t sb = smem_u32(smc);
    const float* wbase = Wg + (size_t)(n0 / cpe) * estride + (size_t)(n0 % cpe);

    const int wm = (wid & 1) * 64, wn = (wid >> 1) * 32;
    const int g = lane >> 2, tg = lane & 3;

    // A loader: rows ar+32i (i<4), 16B chunk akq
    const int ar = tid >> 3, akq = tid & 7;
    const uint32_t* aptr[4];
#pragma unroll
    for (int i = 0; i < 4; i++)
        aptr[i] = Ag + (size_t)(m0 + ar + 32 * i) * lda + akq * 4;
    // B loader: k rows bk+8i (i<4), 16B chunk bnq
    const int bk = tid >> 5, bnq = tid & 31;
    const float* bbase = wbase + (size_t)bk * ldw + bnq * 4;

#define ISSUE(s, kt)                                                             \
    {                                                                            \
        uint32_t ab = sb + (s) * SM_STAGE;                                       \
        _Pragma("unroll")                                                        \
        for (int i = 0; i < 4; i++)                                              \
            cp16(ab + (ar + 32 * i) * (ALD * 4) + akq * 16, aptr[i] + (kt));     \
        uint32_t bb = sb + (s) * SM_STAGE + A_BYTES;                             \
        _Pragma("unroll")                                                        \
        for (int i = 0; i < 4; i++)                                              \
            cp16(bb + (bk + 8 * i) * (BLD * 4) + bnq * 16,                       \
                 bbase + (size_t)((kt) + 8 * i) * ldw);                          \
        CP_COMMIT();                                                             \
    }

    float acc[4][4][4];
#pragma unroll
    for (int i = 0; i < 4; i++)
#pragma unroll
        for (int j = 0; j < 4; j++)
#pragma unroll
            for (int c = 0; c < 4; c++) acc[i][j][c] = 0.f;

    const int KT = Kdim / 32;
    ISSUE(0, 0);
    ISSUE(1, 32);

    for (int ki = 0; ki < KT; ki++) {
        if (ki == KT - 1) { CP_WAIT(0); } else { CP_WAIT(1); }
        __syncthreads();
        if (ki + 2 < KT) ISSUE((ki + 2) % 3, (ki + 2) * 32);

        const uint32_t* As = (const uint32_t*)(smc + (ki % 3) * SM_STAGE);
        const float*    Bs = (const float*)(smc + (ki % 3) * SM_STAGE + A_BYTES);
#pragma unroll
        for (int ks = 0; ks < 4; ks++) {
            const int kb = ks * 8;
            uint32_t a[4][4], b[4][2];
#pragma unroll
            for (int mf = 0; mf < 4; mf++) {
                int r = wm + mf * 16 + g;
                a[mf][0] = As[r * ALD + kb + tg];
                a[mf][1] = As[(r + 8) * ALD + kb + tg];
                a[mf][2] = As[r * ALD + kb + tg + 4];
                a[mf][3] = As[(r + 8) * ALD + kb + tg + 4];
            }
#pragma unroll
            for (int nf = 0; nf < 4; nf++) {
                int c = wn + nf * 8 + g;
                b[nf][0] = f2tf(Bs[(kb + tg) * BLD + c]);
                b[nf][1] = f2tf(Bs[(kb + tg + 4) * BLD + c]);
            }
#pragma unroll
            for (int mf = 0; mf < 4; mf++)
#pragma unroll
                for (int nf = 0; nf < 4; nf++)
                    mma_tf32(acc[mf][nf], a[mf], b[nf]);
        }
    }

#pragma unroll
    for (int mf = 0; mf < 4; mf++) {
        int r0 = m0 + wm + mf * 16 + g;
        int r1 = r0 + 8;
        size_t o0 = (size_t)(rowC ? rowC[r0] : r0) * (size_t)ldc;
        size_t o1 = (size_t)(rowC ? rowC[r1] : r1) * (size_t)ldc;
#pragma unroll
        for (int nf = 0; nf < 4; nf++) {
            int c = n0 + wn + nf * 8 + tg * 2;
            *reinterpret_cast<float2*>(Cg + o0 + c) = make_float2(acc[mf][nf][0], acc[mf][nf][1]);
            *reinterpret_cast<float2*>(Cg + o1 + c) = make_float2(acc[mf][nf][2], acc[mf][nf][3]);
        }
    }
#undef ISSUE
}

// gather h rows by index + convert to tf32 bits
__global__ void gather_tf32(const float* __restrict__ h, const int* __restrict__ idx,
                            uint32_t* __restrict__ dst)
{
    const int r = blockIdx.x;
    const float4* s = reinterpret_cast<const float4*>(h + (size_t)idx[r] * DDIM);
    uint4* d = reinterpret_cast<uint4*>(dst + (size_t)r * DDIM);
    for (int i = threadIdx.x; i < DDIM / 4; i += 256) {
        float4 v = s[i];
        uint4 o;
        o.x = f2tf(v.x); o.y = f2tf(v.y); o.z = f2tf(v.z); o.w = f2tf(v.w);
        d[i] = o;
    }
}

// ---------------------------------------------------------------------------
// gate[m, :] = softmax(h[midx[m]] @ Wr + br)
// ---------------------------------------------------------------------------
__global__ void gate_kernel(const float* __restrict__ h, const int* __restrict__ midx,
                            const float* __restrict__ Wr, const float* __restrict__ br,
                            float* __restrict__ gate)
{
    const int m = blockIdx.x;
    const int tid = threadIdx.x;
    const float* hp = h + (size_t)midx[m] * DDIM;

    float acc[KEXP];
#pragma unroll
    for (int e = 0; e < KEXP; e++) acc[e] = 0.f;
    for (int d = tid; d < DDIM; d += 256) {
        float hv = hp[d];
        const float4* wr = reinterpret_cast<const float4*>(Wr + (size_t)d * KEXP);
        float4 w0 = wr[0], w1 = wr[1];
        acc[0] += hv * w0.x; acc[1] += hv * w0.y; acc[2] += hv * w0.z; acc[3] += hv * w0.w;
        acc[4] += hv * w1.x; acc[5] += hv * w1.y; acc[6] += hv * w1.z; acc[7] += hv * w1.w;
    }
#pragma unroll
    for (int off = 16; off > 0; off >>= 1)
#pragma unroll
        for (int e = 0; e < KEXP; e++)
            acc[e] += __shfl_down_sync(0xffffffffu, acc[e], off);

    __shared__ float ws[8][KEXP];
    const int w = tid >> 5, lane = tid & 31;
    if (lane == 0)
#pragma unroll
        for (int e = 0; e < KEXP; e++) ws[w][e] = acc[e];
    __syncthreads();
    if (tid == 0) {
        float l[KEXP];
#pragma unroll
        for (int e = 0; e < KEXP; e++) {
            float s = br[e];
#pragma unroll
            for (int ww = 0; ww < 8; ww++) s += ws[ww][e];
            l[e] = s;
        }
        float mx = l[0];
#pragma unroll
        for (int e = 1; e < KEXP; e++) mx = fmaxf(mx, l[e]);
        float sum = 0.f;
#pragma unroll
        for (int e = 0; e < KEXP; e++) { l[e] = expf(l[e] - mx); sum += l[e]; }
        float inv = 1.f / sum;
#pragma unroll
        for (int e = 0; e < KEXP; e++) gate[m * KEXP + e] = l[e] * inv;
    }
}

// ---------------------------------------------------------------------------
// per-mask pair scores + segment softmax (anchors u = m-5 .. m+4 in [0,UPOS))
// ---------------------------------------------------------------------------
__global__ void score_combine(const float* __restrict__ q, const float* __restrict__ k,
                              const float* __restrict__ bq, const float* __restrict__ bk,
                              float* __restrict__ cmb)
{
    const int m = blockIdx.x;
    const int w = threadIdx.x >> 5;    // 0..9
    const int lane = threadIdx.x & 31;
    const int u = m - 5 + w;
    const bool valid = (u >= 0) && (u < UPOS);

    __shared__ float sc[10];
    float s = 0.f;
    if (valid) {
        const float* qp = q + (size_t)m * DPROJ;
        const float* kp = k + (size_t)u * DPROJ;
        for (int i = lane; i < DPROJ; i += 32)
            s += (qp[i] + bq[i]) * (kp[i] + bk[i]);
#pragma unroll
        for (int off = 16; off > 0; off >>= 1)
            s += __shfl_down_sync(0xffffffffu, s, off);
    }
    if (lane == 0) sc[w] = valid ? s * 0.044194173824159216f : -1e30f;
    __syncthreads();
    if (threadIdx.x == 0) {
        float mx = -1e30f;
#pragma unroll
        for (int j = 0; j < 10; j++) mx = fmaxf(mx, sc[j]);
        float e[10]; float sum = 0.f;
#pragma unroll
        for (int j = 0; j < 10; j++) {
            e[j] = (sc[j] > -1e29f) ? expf(sc[j] - mx) : 0.f;
            sum += e[j];
        }
        float inv = 1.f / fmaxf(sum, 1e-8f);
#pragma unroll
        for (int j = 0; j < 10; j++) cmb[m * 10 + j] = e[j] * inv;
    }
}

// ---------------------------------------------------------------------------
// g_G[m, n] = tf32( gate[m][n/H] * sum_j cmb[m][j] * gelu(A[u_j,n]+B[m,n]+b1[n]) )
// ---------------------------------------------------------------------------
__global__ void aggregate_kernel(const float* __restrict__ A, const float* __restrict__ B,
                                 const float* __restrict__ b1, const float* __restrict__ cmb,
                                 const float* __restrict__ gate, uint32_t* __restrict__ G)
{
    const int m = blockIdx.y;
    const int n = blockIdx.x * 256 + threadIdx.x;
    __shared__ float c[10];
    __shared__ int   us[10];
    __shared__ float gt[KEXP];
    if (threadIdx.x < 10) {
        c[threadIdx.x] = cmb[m * 10 + threadIdx.x];
        int u = m - 5 + threadIdx.x;
        us[threadIdx.x] = min(max(u, 0), UPOS - 1);
    }
    if (threadIdx.x < KEXP) gt[threadIdx.x] = gate[m * KEXP + threadIdx.x];
    __syncthreads();

    const float Bv = B[(size_t)m * EHDIM + n] + b1[n];
    float acc = 0.f;
#pragma unroll
    for (int j = 0; j < 10; j++) {
        float x = A[(size_t)us[j] * EHDIM + n] + Bv;
        float ge = 0.5f * x * (1.f + erff(x * 0.70710678118654752f));
        acc = fmaf(c[j], ge, acc);
    }
    G[(size_t)m * EHDIM + n] = f2tf(gt[n >> 11] * acc);
}

// out[midx[m], d] += sum_e gate[m][e] * b2[e][d]
__global__ void addb2_kernel(const float* __restrict__ gate, const float* __restrict__ b2,
                             const int* __restrict__ midx, float* __restrict__ out)
{
    const int m = blockIdx.y;
    const int d = blockIdx.x * 256 + threadIdx.x;
    float s = 0.f;
#pragma unroll
    for (int e = 0; e < KEXP; e++)
        s = fmaf(gate[m * KEXP + e], b2[(size_t)e * DDIM + d], s);
    out[(size_t)midx[m] * DDIM + d] += s;
}

// ---------------------------------------------------------------------------
extern "C" void kernel_launch(void* const* d_in, const int* in_sizes, int n_in,
                              void* d_out, int out_size)
{
    const float* h   = (const float*)d_in[0];
    const int*   midx= (const int*)d_in[1];
    const int*   uidx= (const int*)d_in[2];
    const float* Wr  = (const float*)d_in[4];
    const float* br  = (const float*)d_in[5];
    const float* W1  = (const float*)d_in[6];
    const float* b1  = (const float*)d_in[7];
    const float* W2  = (const float*)d_in[8];
    const float* b2  = (const float*)d_in[9];
    const float* Wq  = (const float*)d_in[10];
    const float* bq  = (const float*)d_in[11];
    const float* Wk  = (const float*)d_in[12];
    const float* bk  = (const float*)d_in[13];
    float* out = (float*)d_out;

    float *pA, *pB, *pq, *pk, *pgate, *pcmb;
    uint32_t *pG, *phM, *phU;
    cudaGetSymbolAddress((void**)&pA, g_A);
    cudaGetSymbolAddress((void**)&pB, g_B);
    cudaGetSymbolAddress((void**)&pG, g_G);
    cudaGetSymbolAddress((void**)&phM, g_hM);
    cudaGetSymbolAddress((void**)&phU, g_hU);
    cudaGetSymbolAddress((void**)&pq, g_q);
    cudaGetSymbolAddress((void**)&pk, g_k);
    cudaGetSymbolAddress((void**)&pgate, g_gate);
    cudaGetSymbolAddress((void**)&pcmb, g_cmb);

    cudaFuncSetAttribute(gemm_cp, cudaFuncAttributeMaxDynamicSharedMemorySize, SM_TOTAL);

    // zero output (odd rows stay zero; even rows overwritten by final GEMM)
    cudaMemsetAsync(out, 0, (size_t)out_size * sizeof(float));

    // gather + convert h rows (A operands; weights stay raw fp32)
    gather_tf32<<<MPOS, 256>>>(h, midx, phM);
    gather_tf32<<<UPOS, 256>>>(h, uidx, phU);

    // gate (fp32)
    gate_kernel<<<MPOS, 256>>>(h, midx, Wr, br, pgate);

    // q = hM @ Wq ; k = hU @ Wk  (batched via blockIdx.z)
    gemm_cp<<<dim3(MPOS / 128, DPROJ / 128, 2), 256, SM_TOTAL>>>(
        phM, DDIM, Wq, DPROJ, DPROJ, 0, pq, DPROJ, nullptr, DDIM,
        phU, Wk, pk);

    // per-mask segment softmax over <=10 anchors
    score_combine<<<MPOS, 320>>>(pq, pk, bq, bk, pcmb);

    // A = hU @ W1_top ; B = hM @ W1_bot   (expert-strided columns, cpe=HHID)
    gemm_cp<<<dim3(UPOS / 128, EHDIM / 128, 1), 256, SM_TOTAL>>>(
        phU, DDIM, W1, HHID, HHID, (size_t)2 * DDIM * HHID, pA, EHDIM, nullptr, DDIM,
        nullptr, nullptr, nullptr);
    gemm_cp<<<dim3(MPOS / 128, EHDIM / 128, 1), 256, SM_TOTAL>>>(
        phM, DDIM, W1 + (size_t)DDIM * HHID, HHID, HHID, (size_t)2 * DDIM * HHID,
        pB, EHDIM, nullptr, DDIM,
        nullptr, nullptr, nullptr);

    // gelu + combine aggregation, gate folded in, tf32 output
    aggregate_kernel<<<dim3(EHDIM / 256, MPOS), 256>>>(pA, pB, b1, pcmb, pgate, pG);

    // out[masks] = G @ W2_flat   (K = 16384, W2 flat contiguous [16384 x 4096])
    gemm_cp<<<dim3(MPOS / 128, DDIM / 128, 1), 256, SM_TOTAL>>>(
        pG, EHDIM, W2, DDIM, DDIM, 0, out, DDIM, midx, EHDIM,
        nullptr, nullptr, nullptr);

    // + sum_e gate*b2 (combine weights sum to 1 per mask)
    addb2_kernel<<<dim3(DDIM / 256, MPOS), 256>>>(pgate, b2, midx, out);
}

// round 7
// speedup vs baseline: 1.1123x; 1.0030x over previous
#include <cuda_runtime.h>
#include <cstdint>

// Problem constants (fixed by setup_inputs)
#define LDIM 2048
#define DDIM 4096
#define KEXP 8
#define MPOS 1024
#define UPOS 1024
#define DPROJ 512
#define HHID 2048
#define EHDIM 16384   // KEXP * HHID

// ---------------------------------------------------------------------------
// Device-global scratch (no runtime allocation allowed)
// ---------------------------------------------------------------------------
__device__ float    g_A[(size_t)UPOS * EHDIM];    // anchors @ W1_top
__device__ float    g_B[(size_t)MPOS * EHDIM];    // masks   @ W1_bot
__device__ uint32_t g_G[(size_t)MPOS * EHDIM];    // tf32 bits of gated/combined gelu
__device__ uint32_t g_hM[(size_t)MPOS * DDIM];    // tf32 gathered mask rows of h
__device__ uint32_t g_hU[(size_t)UPOS * DDIM];    // tf32 gathered anchor rows of h
__device__ float    g_q[MPOS * DPROJ];
__device__ float    g_k[UPOS * DPROJ];
__device__ float    g_gate[MPOS * KEXP];
__device__ float    g_cmb[MPOS * 10];

// ---------------------------------------------------------------------------
// helpers
// ---------------------------------------------------------------------------
__device__ __forceinline__ uint32_t f2tf(float x) {
    uint32_t r;
    asm("cvt.rna.tf32.f32 %0, %1;" : "=r"(r) : "f"(x));
    return r;
}
__device__ __forceinline__ uint32_t smem_u32(const void* p) {
    uint32_t a;
    asm("{ .reg .u64 t; cvta.to.shared.u64 t, %1; cvt.u32.u64 %0, t; }" : "=r"(a) : "l"(p));
    return a;
}
__device__ __forceinline__ void cp16(uint32_t dst, const void* src) {
    asm volatile("cp.async.cg.shared.global [%0], [%1], 16;" :: "r"(dst), "l"(src));
}
#define CP_COMMIT() asm volatile("cp.async.commit_group;" ::: "memory")
#define CP_WAIT(n)  asm volatile("cp.async.wait_group %0;" :: "n"(n) : "memory")

__device__ __forceinline__ void ldsm_x4(uint32_t* r, uint32_t addr) {
    asm volatile("ldmatrix.sync.aligned.m8n8.x4.shared.b16 {%0,%1,%2,%3}, [%4];"
                 : "=r"(r[0]), "=r"(r[1]), "=r"(r[2]), "=r"(r[3]) : "r"(addr));
}

__device__ __forceinline__ void mma_tf32(float* c, const uint32_t* a, const uint32_t* b) {
    asm volatile(
        "mma.sync.aligned.m16n8k8.row.col.f32.tf32.tf32.f32 "
        "{%0,%1,%2,%3}, {%4,%5,%6,%7}, {%8,%9}, {%0,%1,%2,%3};\n"
        : "+f"(c[0]), "+f"(c[1]), "+f"(c[2]), "+f"(c[3])
        : "r"(a[0]), "r"(a[1]), "r"(a[2]), "r"(a[3]), "r"(b[0]), "r"(b[1]));
}

// smem stage layout (bytes):
//   A tile: [128 m][36 words]  rows 144 B (ldmatrix phases hit banks 4l..4l+3, CF)
//   B tile: [32 k][136 words]  rows 544 B (136 mod 32 = 8 -> banks 8tg+g, CF)
#define ALD 36
#define BLD 136
#define A_BYTES (128 * ALD * 4)          // 18432
#define B_BYTES (32 * BLD * 4)           // 17408
#define SM_STAGE (A_BYTES + B_BYTES)     // 35840
#define SM_TOTAL (3 * SM_STAGE)          // 107520

// ---------------------------------------------------------------------------
// tf32 GEMM, cp.async 3-stage pipeline, ldmatrix A-fragment loads.
// C[m, n] = sum_k A(m)[k] * W(k, n)
//   A operand: pre-converted tf32 bits.
//   W operand: RAW fp32, converted to tf32 (RNA) at fragment-load time.
// BM=BN=128, BK=32, 256 threads, 8 warps each 64x32 via m16n8k8.
// grid = (M/128, N/128 [, 2]); blockIdx.z==1 selects (Ag2, Wg2, Cg2).
// ---------------------------------------------------------------------------
__global__ __launch_bounds__(256, 2)
void gemm_cp(const uint32_t* __restrict__ Ag, int lda,
             const float* __restrict__ Wg, int ldw, int cpe, size_t estride,
             float* __restrict__ Cg, int ldc, const int* __restrict__ rowC,
             int Kdim,
             const uint32_t* __restrict__ Ag2, const float* __restrict__ Wg2,
             float* __restrict__ Cg2)
{
    extern __shared__ char smc[];

    if (blockIdx.z) { Ag = Ag2; Wg = Wg2; Cg = Cg2; }

    const int tid = threadIdx.x, lane = tid & 31, wid = tid >> 5;
    const int m0 = blockIdx.x * 128, n0 = blockIdx.y * 128;
    const uint32_t sb = smem_u32(smc);
    const float* wbase = Wg + (size_t)(n0 / cpe) * estride + (size_t)(n0 % cpe);

    const int wm = (wid & 1) * 64, wn = (wid >> 1) * 32;
    const int g = lane >> 2, tg = lane & 3;

    // per-thread ldmatrix address offset within the A tile:
    //   row = wm + (lane & 15), col-half = (lane >> 4) * 16 bytes
    const uint32_t aoff = (uint32_t)(wm + (lane & 15)) * (ALD * 4) + (lane >> 4) * 16;

    // A loader: rows ar+32i (i<4), 16B chunk akq
    const int ar = tid >> 3, akq = tid & 7;
    const uint32_t* aptr[4];
#pragma unroll
    for (int i = 0; i < 4; i++)
        aptr[i] = Ag + (size_t)(m0 + ar + 32 * i) * lda + akq * 4;
    // B loader: k rows bk+8i (i<4), 16B chunk bnq
    const int bk = tid >> 5, bnq = tid & 31;
    const float* bbase = wbase + (size_t)bk * ldw + bnq * 4;

#define ISSUE(s, kt)                                                             \
    {                                                                            \
        uint32_t ab = sb + (s) * SM_STAGE;                                       \
        _Pragma("unroll")                                                        \
        for (int i = 0; i < 4; i++)                                              \
            cp16(ab + (ar + 32 * i) * (ALD * 4) + akq * 16, aptr[i] + (kt));     \
        uint32_t bb = sb + (s) * SM_STAGE + A_BYTES;                             \
        _Pragma("unroll")                                                        \
        for (int i = 0; i < 4; i++)                                              \
            cp16(bb + (bk + 8 * i) * (BLD * 4) + bnq * 16,                       \
                 bbase + (size_t)((kt) + 8 * i) * ldw);                          \
        CP_COMMIT();                                                             \
    }

    float acc[4][4][4];
#pragma unroll
    for (int i = 0; i < 4; i++)
#pragma unroll
        for (int j = 0; j < 4; j++)
#pragma unroll
            for (int c = 0; c < 4; c++) acc[i][j][c] = 0.f;

    const int KT = Kdim / 32;
    ISSUE(0, 0);
    ISSUE(1, 32);

    for (int ki = 0; ki < KT; ki++) {
        if (ki == KT - 1) { CP_WAIT(0); } else { CP_WAIT(1); }
        __syncthreads();
        if (ki + 2 < KT) ISSUE((ki + 2) % 3, (ki + 2) * 32);

        const uint32_t abase = sb + (ki % 3) * SM_STAGE + aoff;
        const float*   Bs = (const float*)(smc + (ki % 3) * SM_STAGE + A_BYTES);
#pragma unroll
        for (int ks = 0; ks < 4; ks++) {
            const int kb = ks * 8;
            uint32_t a[4][4], b[4][2];
#pragma unroll
            for (int mf = 0; mf < 4; mf++)
                ldsm_x4(a[mf], abase + mf * (16 * ALD * 4) + ks * 32);
#pragma unroll
            for (int nf = 0; nf < 4; nf++) {
                int c = wn + nf * 8 + g;
                b[nf][0] = f2tf(Bs[(kb + tg) * BLD + c]);
                b[nf][1] = f2tf(Bs[(kb + tg + 4) * BLD + c]);
            }
#pragma unroll
            for (int mf = 0; mf < 4; mf++)
#pragma unroll
                for (int nf = 0; nf < 4; nf++)
                    mma_tf32(acc[mf][nf], a[mf], b[nf]);
        }
    }

#pragma unroll
    for (int mf = 0; mf < 4; mf++) {
        int r0 = m0 + wm + mf * 16 + g;
        int r1 = r0 + 8;
        size_t o0 = (size_t)(rowC ? rowC[r0] : r0) * (size_t)ldc;
        size_t o1 = (size_t)(rowC ? rowC[r1] : r1) * (size_t)ldc;
#pragma unroll
        for (int nf = 0; nf < 4; nf++) {
            int c = n0 + wn + nf * 8 + tg * 2;
            *reinterpret_cast<float2*>(Cg + o0 + c) = make_float2(acc[mf][nf][0], acc[mf][nf][1]);
            *reinterpret_cast<float2*>(Cg + o1 + c) = make_float2(acc[mf][nf][2], acc[mf][nf][3]);
        }
    }
#undef ISSUE
}

// gather h rows by index + convert to tf32 bits
__global__ void gather_tf32(const float* __restrict__ h, const int* __restrict__ idx,
                            uint32_t* __restrict__ dst)
{
    const int r = blockIdx.x;
    const float4* s = reinterpret_cast<const float4*>(h + (size_t)idx[r] * DDIM);
    uint4* d = reinterpret_cast<uint4*>(dst + (size_t)r * DDIM);
    for (int i = threadIdx.x; i < DDIM / 4; i += 256) {
        float4 v = s[i];
        uint4 o;
        o.x = f2tf(v.x); o.y = f2tf(v.y); o.z = f2tf(v.z); o.w = f2tf(v.w);
        d[i] = o;
    }
}

// ---------------------------------------------------------------------------
// gate[m, :] = softmax(h[midx[m]] @ Wr + br)
// ---------------------------------------------------------------------------
__global__ void gate_kernel(const float* __restrict__ h, const int* __restrict__ midx,
                            const float* __restrict__ Wr, const float* __restrict__ br,
                            float* __restrict__ gate)
{
    const int m = blockIdx.x;
    const int tid = threadIdx.x;
    const float* hp = h + (size_t)midx[m] * DDIM;

    float acc[KEXP];
#pragma unroll
    for (int e = 0; e < KEXP; e++) acc[e] = 0.f;
    for (int d = tid; d < DDIM; d += 256) {
        float hv = hp[d];
        const float4* wr = reinterpret_cast<const float4*>(Wr + (size_t)d * KEXP);
        float4 w0 = wr[0], w1 = wr[1];
        acc[0] += hv * w0.x; acc[1] += hv * w0.y; acc[2] += hv * w0.z; acc[3] += hv * w0.w;
        acc[4] += hv * w1.x; acc[5] += hv * w1.y; acc[6] += hv * w1.z; acc[7] += hv * w1.w;
    }
#pragma unroll
    for (int off = 16; off > 0; off >>= 1)
#pragma unroll
        for (int e = 0; e < KEXP; e++)
            acc[e] += __shfl_down_sync(0xffffffffu, acc[e], off);

    __shared__ float ws[8][KEXP];
    const int w = tid >> 5, lane = tid & 31;
    if (lane == 0)
#pragma unroll
        for (int e = 0; e < KEXP; e++) ws[w][e] = acc[e];
    __syncthreads();
    if (tid == 0) {
        float l[KEXP];
#pragma unroll
        for (int e = 0; e < KEXP; e++) {
            float s = br[e];
#pragma unroll
            for (int ww = 0; ww < 8; ww++) s += ws[ww][e];
            l[e] = s;
        }
        float mx = l[0];
#pragma unroll
        for (int e = 1; e < KEXP; e++) mx = fmaxf(mx, l[e]);
        float sum = 0.f;
#pragma unroll
        for (int e = 0; e < KEXP; e++) { l[e] = expf(l[e] - mx); sum += l[e]; }
        float inv = 1.f / sum;
#pragma unroll
        for (int e = 0; e < KEXP; e++) gate[m * KEXP + e] = l[e] * inv;
    }
}

// ---------------------------------------------------------------------------
// per-mask pair scores + segment softmax (anchors u = m-5 .. m+4 in [0,UPOS))
// ---------------------------------------------------------------------------
__global__ void score_combine(const float* __restrict__ q, const float* __restrict__ k,
                              const float* __restrict__ bq, const float* __restrict__ bk,
                              float* __restrict__ cmb)
{
    const int m = blockIdx.x;
    const int w = threadIdx.x >> 5;    // 0..9
    const int lane = threadIdx.x & 31;
    const int u = m - 5 + w;
    const bool valid = (u >= 0) && (u < UPOS);

    __shared__ float sc[10];
    float s = 0.f;
    if (valid) {
        const float* qp = q + (size_t)m * DPROJ;
        const float* kp = k + (size_t)u * DPROJ;
        for (int i = lane; i < DPROJ; i += 32)
            s += (qp[i] + bq[i]) * (kp[i] + bk[i]);
#pragma unroll
        for (int off = 16; off > 0; off >>= 1)
            s += __shfl_down_sync(0xffffffffu, s, off);
    }
    if (lane == 0) sc[w] = valid ? s * 0.044194173824159216f : -1e30f;
    __syncthreads();
    if (threadIdx.x == 0) {
        float mx = -1e30f;
#pragma unroll
        for (int j = 0; j < 10; j++) mx = fmaxf(mx, sc[j]);
        float e[10]; float sum = 0.f;
#pragma unroll
        for (int j = 0; j < 10; j++) {
            e[j] = (sc[j] > -1e29f) ? expf(sc[j] - mx) : 0.f;
            sum += e[j];
        }
        float inv = 1.f / fmaxf(sum, 1e-8f);
#pragma unroll
        for (int j = 0; j < 10; j++) cmb[m * 10 + j] = e[j] * inv;
    }
}

// ---------------------------------------------------------------------------
// g_G[m, n] = tf32( gate[m][n/H] * sum_j cmb[m][j] * gelu(A[u_j,n]+B[m,n]+b1[n]) )
// ---------------------------------------------------------------------------
__global__ void aggregate_kernel(const float* __restrict__ A, const float* __restrict__ B,
                                 const float* __restrict__ b1, const float* __restrict__ cmb,
                                 const float* __restrict__ gate, uint32_t* __restrict__ G)
{
    const int m = blockIdx.y;
    const int n = blockIdx.x * 256 + threadIdx.x;
    __shared__ float c[10];
    __shared__ int   us[10];
    __shared__ float gt[KEXP];
    if (threadIdx.x < 10) {
        c[threadIdx.x] = cmb[m * 10 + threadIdx.x];
        int u = m - 5 + threadIdx.x;
        us[threadIdx.x] = min(max(u, 0), UPOS - 1);
    }
    if (threadIdx.x < KEXP) gt[threadIdx.x] = gate[m * KEXP + threadIdx.x];
    __syncthreads();

    const float Bv = B[(size_t)m * EHDIM + n] + b1[n];
    float acc = 0.f;
#pragma unroll
    for (int j = 0; j < 10; j++) {
        float x = A[(size_t)us[j] * EHDIM + n] + Bv;
        float ge = 0.5f * x * (1.f + erff(x * 0.70710678118654752f));
        acc = fmaf(c[j], ge, acc);
    }
    G[(size_t)m * EHDIM + n] = f2tf(gt[n >> 11] * acc);
}

// out[midx[m], d] += sum_e gate[m][e] * b2[e][d]
__global__ void addb2_kernel(const float* __restrict__ gate, const float* __restrict__ b2,
                             const int* __restrict__ midx, float* __restrict__ out)
{
    const int m = blockIdx.y;
    const int d = blockIdx.x * 256 + threadIdx.x;
    float s = 0.f;
#pragma unroll
    for (int e = 0; e < KEXP; e++)
        s = fmaf(gate[m * KEXP + e], b2[(size_t)e * DDIM + d], s);
    out[(size_t)midx[m] * DDIM + d] += s;
}

// ---------------------------------------------------------------------------
extern "C" void kernel_launch(void* const* d_in, const int* in_sizes, int n_in,
                              void* d_out, int out_size)
{
    const float* h   = (const float*)d_in[0];
    const int*   midx= (const int*)d_in[1];
    const int*   uidx= (const int*)d_in[2];
    const float* Wr  = (const float*)d_in[4];
    const float* br  = (const float*)d_in[5];
    const float* W1  = (const float*)d_in[6];
    const float* b1  = (const float*)d_in[7];
    const float* W2  = (const float*)d_in[8];
    const float* b2  = (const float*)d_in[9];
    const float* Wq  = (const float*)d_in[10];
    const float* bq  = (const float*)d_in[11];
    const float* Wk  = (const float*)d_in[12];
    const float* bk  = (const float*)d_in[13];
    float* out = (float*)d_out;

    float *pA, *pB, *pq, *pk, *pgate, *pcmb;
    uint32_t *pG, *phM, *phU;
    cudaGetSymbolAddress((void**)&pA, g_A);
    cudaGetSymbolAddress((void**)&pB, g_B);
    cudaGetSymbolAddress((void**)&pG, g_G);
    cudaGetSymbolAddress((void**)&phM, g_hM);
    cudaGetSymbolAddress((void**)&phU, g_hU);
    cudaGetSymbolAddress((void**)&pq, g_q);
    cudaGetSymbolAddress((void**)&pk, g_k);
    cudaGetSymbolAddress((void**)&pgate, g_gate);
    cudaGetSymbolAddress((void**)&pcmb, g_cmb);

    cudaFuncSetAttribute(gemm_cp, cudaFuncAttributeMaxDynamicSharedMemorySize, SM_TOTAL);

    // zero output (odd rows stay zero; even rows overwritten by final GEMM)
    cudaMemsetAsync(out, 0, (size_t)out_size * sizeof(float));

    // gather + convert h rows (A operands; weights stay raw fp32)
    gather_tf32<<<MPOS, 256>>>(h, midx, phM);
    gather_tf32<<<UPOS, 256>>>(h, uidx, phU);

    // gate (fp32)
    gate_kernel<<<MPOS, 256>>>(h, midx, Wr, br, pgate);

    // q = hM @ Wq ; k = hU @ Wk  (batched via blockIdx.z)
    gemm_cp<<<dim3(MPOS / 128, DPROJ / 128, 2), 256, SM_TOTAL>>>(
        phM, DDIM, Wq, DPROJ, DPROJ, 0, pq, DPROJ, nullptr, DDIM,
        phU, Wk, pk);

    // per-mask segment softmax over <=10 anchors
    score_combine<<<MPOS, 320>>>(pq, pk, bq, bk, pcmb);

    // A = hU @ W1_top ; B = hM @ W1_bot — merged into ONE launch via blockIdx.z
    gemm_cp<<<dim3(UPOS / 128, EHDIM / 128, 2), 256, SM_TOTAL>>>(
        phU, DDIM, W1, HHID, HHID, (size_t)2 * DDIM * HHID, pA, EHDIM, nullptr, DDIM,
        phM, W1 + (size_t)DDIM * HHID, pB);

    // gelu + combine aggregation, gate folded in, tf32 output
    aggregate_kernel<<<dim3(EHDIM / 256, MPOS), 256>>>(pA, pB, b1, pcmb, pgate, pG);

    // out[masks] = G @ W2_flat   (K = 16384, W2 flat contiguous [16384 x 4096])
    gemm_cp<<<dim3(MPOS / 128, DDIM / 128, 1), 256, SM_TOTAL>>>(
        pG, EHDIM, W2, DDIM, DDIM, 0, out, DDIM, midx, EHDIM,
        nullptr, nullptr, nullptr);

    // + sum_e gate*b2 (combine weights sum to 1 per mask)
    addb2_kernel<<<dim3(DDIM / 256, MPOS), 256>>>(pgate, b2, midx, out);
}

// round 8
// speedup vs baseline: 1.1256x; 1.0120x over previous
#include <cuda_runtime.h>
#include <cstdint>

// Problem constants (fixed by setup_inputs)
#define LDIM 2048
#define DDIM 4096
#define KEXP 8
#define MPOS 1024
#define UPOS 1024
#define DPROJ 512
#define HHID 2048
#define EHDIM 16384   // KEXP * HHID

// ---------------------------------------------------------------------------
// Device-global scratch (no runtime allocation allowed)
// ---------------------------------------------------------------------------
__device__ float    g_A[(size_t)UPOS * EHDIM];    // anchors @ W1_top
__device__ float    g_B[(size_t)MPOS * EHDIM];    // masks   @ W1_bot
__device__ uint32_t g_G[(size_t)MPOS * EHDIM];    // tf32 bits of gated/combined gelu
__device__ uint32_t g_hM[(size_t)MPOS * DDIM];    // tf32 gathered mask rows of h
__device__ uint32_t g_hU[(size_t)UPOS * DDIM];    // tf32 gathered anchor rows of h
__device__ float    g_q[MPOS * DPROJ];
__device__ float    g_k[UPOS * DPROJ];
__device__ float    g_gate[MPOS * KEXP];
__device__ float    g_cmb[MPOS * 10];

// ---------------------------------------------------------------------------
// helpers
// ---------------------------------------------------------------------------
__device__ __forceinline__ uint32_t f2tf(float x) {
    uint32_t r;
    asm("cvt.rna.tf32.f32 %0, %1;" : "=r"(r) : "f"(x));
    return r;
}
__device__ __forceinline__ uint32_t smem_u32(const void* p) {
    uint32_t a;
    asm("{ .reg .u64 t; cvta.to.shared.u64 t, %1; cvt.u32.u64 %0, t; }" : "=r"(a) : "l"(p));
    return a;
}
__device__ __forceinline__ void cp16(uint32_t dst, const void* src) {
    asm volatile("cp.async.cg.shared.global [%0], [%1], 16;" :: "r"(dst), "l"(src));
}
#define CP_COMMIT() asm volatile("cp.async.commit_group;" ::: "memory")
#define CP_WAIT(n)  asm volatile("cp.async.wait_group %0;" :: "n"(n) : "memory")

__device__ __forceinline__ void ldsm_x4(uint32_t* r, uint32_t addr) {
    asm volatile("ldmatrix.sync.aligned.m8n8.x4.shared.b16 {%0,%1,%2,%3}, [%4];"
                 : "=r"(r[0]), "=r"(r[1]), "=r"(r[2]), "=r"(r[3]) : "r"(addr));
}

__device__ __forceinline__ void mma_tf32(float* c, const uint32_t* a, const uint32_t* b) {
    asm volatile(
        "mma.sync.aligned.m16n8k8.row.col.f32.tf32.tf32.f32 "
        "{%0,%1,%2,%3}, {%4,%5,%6,%7}, {%8,%9}, {%0,%1,%2,%3};\n"
        : "+f"(c[0]), "+f"(c[1]), "+f"(c[2]), "+f"(c[3])
        : "r"(a[0]), "r"(a[1]), "r"(a[2]), "r"(a[3]), "r"(b[0]), "r"(b[1]));
}

// smem stage layout (bytes):
//   A tile: [128 m][36 words]  rows 144 B (ldmatrix phases hit banks 4l..4l+3, CF)
//   B tile: [32 k][136 words]  rows 544 B (136 mod 32 = 8 -> banks 8tg+g, CF)
#define ALD 36
#define BLD 136
#define A_BYTES (128 * ALD * 4)          // 18432
#define B_BYTES (32 * BLD * 4)           // 17408
#define SM_STAGE (A_BYTES + B_BYTES)     // 35840
#define SM_TOTAL (3 * SM_STAGE)          // 107520

// ---------------------------------------------------------------------------
// tf32 GEMM, cp.async 3-stage pipeline, ldmatrix A-fragment loads.
// C[m, n] = sum_k A(m)[k] * W(k, n)
//   A operand: pre-converted tf32 bits.
//   W operand: RAW fp32, converted to tf32 (RNA) at fragment-load time.
// BM=BN=128, BK=32; 128 threads; 4 warps (2x2) each 64x64 via m16n8k8.
// grid = (M/128, N/128 [, 2]); blockIdx.z==1 selects (Ag2, Wg2, Cg2).
// ---------------------------------------------------------------------------
__global__ __launch_bounds__(128, 2)
void gemm_cp(const uint32_t* __restrict__ Ag, int lda,
             const float* __restrict__ Wg, int ldw, int cpe, size_t estride,
             float* __restrict__ Cg, int ldc, const int* __restrict__ rowC,
             int Kdim,
             const uint32_t* __restrict__ Ag2, const float* __restrict__ Wg2,
             float* __restrict__ Cg2)
{
    extern __shared__ char smc[];

    if (blockIdx.z) { Ag = Ag2; Wg = Wg2; Cg = Cg2; }

    const int tid = threadIdx.x, lane = tid & 31, wid = tid >> 5;
    const int m0 = blockIdx.x * 128, n0 = blockIdx.y * 128;
    const uint32_t sb = smem_u32(smc);
    const float* wbase = Wg + (size_t)(n0 / cpe) * estride + (size_t)(n0 % cpe);

    const int wm = (wid & 1) * 64, wn = (wid >> 1) * 64;
    const int g = lane >> 2, tg = lane & 3;

    // per-thread ldmatrix address offset within the A tile:
    //   row = wm + (lane & 15), col-half = (lane >> 4) * 16 bytes
    const uint32_t aoff = (uint32_t)(wm + (lane & 15)) * (ALD * 4) + (lane >> 4) * 16;

    // A loader: rows ar+16i (i<8), 16B chunk akq
    const int ar = tid >> 3, akq = tid & 7;     // ar 0..15
    const uint32_t* aptr[8];
#pragma unroll
    for (int i = 0; i < 8; i++)
        aptr[i] = Ag + (size_t)(m0 + ar + 16 * i) * lda + akq * 4;
    // B loader: k rows bk+4i (i<8), 16B chunk bnq
    const int bk = tid >> 5, bnq = tid & 31;    // bk 0..3
    const float* bbase = wbase + (size_t)bk * ldw + bnq * 4;

#define ISSUE(s, kt)                                                             \
    {                                                                            \
        uint32_t ab = sb + (s) * SM_STAGE;                                       \
        _Pragma("unroll")                                                        \
        for (int i = 0; i < 8; i++)                                              \
            cp16(ab + (ar + 16 * i) * (ALD * 4) + akq * 16, aptr[i] + (kt));     \
        uint32_t bb = sb + (s) * SM_STAGE + A_BYTES;                             \
        _Pragma("unroll")                                                        \
        for (int i = 0; i < 8; i++)                                              \
            cp16(bb + (bk + 4 * i) * (BLD * 4) + bnq * 16,                       \
                 bbase + (size_t)((kt) + 4 * i) * ldw);                          \
        CP_COMMIT();                                                             \
    }

    float acc[4][8][4];
#pragma unroll
    for (int i = 0; i < 4; i++)
#pragma unroll
        for (int j = 0; j < 8; j++)
#pragma unroll
            for (int c = 0; c < 4; c++) acc[i][j][c] = 0.f;

    const int KT = Kdim / 32;
    ISSUE(0, 0);
    ISSUE(1, 32);

    for (int ki = 0; ki < KT; ki++) {
        if (ki == KT - 1) { CP_WAIT(0); } else { CP_WAIT(1); }
        __syncthreads();
        if (ki + 2 < KT) ISSUE((ki + 2) % 3, (ki + 2) * 32);

        const uint32_t abase = sb + (ki % 3) * SM_STAGE + aoff;
        const float*   Bs = (const float*)(smc + (ki % 3) * SM_STAGE + A_BYTES);
#pragma unroll
        for (int ks = 0; ks < 4; ks++) {
            const int kb = ks * 8;
            uint32_t a[4][4], b[8][2];
#pragma unroll
            for (int mf = 0; mf < 4; mf++)
                ldsm_x4(a[mf], abase + mf * (16 * ALD * 4) + ks * 32);
#pragma unroll
            for (int nf = 0; nf < 8; nf++) {
                int c = wn + nf * 8 + g;
                b[nf][0] = f2tf(Bs[(kb + tg) * BLD + c]);
                b[nf][1] = f2tf(Bs[(kb + tg + 4) * BLD + c]);
            }
#pragma unroll
            for (int mf = 0; mf < 4; mf++)
#pragma unroll
                for (int nf = 0; nf < 8; nf++)
                    mma_tf32(acc[mf][nf], a[mf], b[nf]);
        }
    }

#pragma unroll
    for (int mf = 0; mf < 4; mf++) {
        int r0 = m0 + wm + mf * 16 + g;
        int r1 = r0 + 8;
        size_t o0 = (size_t)(rowC ? rowC[r0] : r0) * (size_t)ldc;
        size_t o1 = (size_t)(rowC ? rowC[r1] : r1) * (size_t)ldc;
#pragma unroll
        for (int nf = 0; nf < 8; nf++) {
            int c = n0 + wn + nf * 8 + tg * 2;
            *reinterpret_cast<float2*>(Cg + o0 + c) = make_float2(acc[mf][nf][0], acc[mf][nf][1]);
            *reinterpret_cast<float2*>(Cg + o1 + c) = make_float2(acc[mf][nf][2], acc[mf][nf][3]);
        }
    }
#undef ISSUE
}

// gather h rows by index + convert to tf32 bits
__global__ void gather_tf32(const float* __restrict__ h, const int* __restrict__ idx,
                            uint32_t* __restrict__ dst)
{
    const int r = blockIdx.x;
    const float4* s = reinterpret_cast<const float4*>(h + (size_t)idx[r] * DDIM);
    uint4* d = reinterpret_cast<uint4*>(dst + (size_t)r * DDIM);
    for (int i = threadIdx.x; i < DDIM / 4; i += 256) {
        float4 v = s[i];
        uint4 o;
        o.x = f2tf(v.x); o.y = f2tf(v.y); o.z = f2tf(v.z); o.w = f2tf(v.w);
        d[i] = o;
    }
}

// ---------------------------------------------------------------------------
// gate[m, :] = softmax(h[midx[m]] @ Wr + br)
// ---------------------------------------------------------------------------
__global__ void gate_kernel(const float* __restrict__ h, const int* __restrict__ midx,
                            const float* __restrict__ Wr, const float* __restrict__ br,
                            float* __restrict__ gate)
{
    const int m = blockIdx.x;
    const int tid = threadIdx.x;
    const float* hp = h + (size_t)midx[m] * DDIM;

    float acc[KEXP];
#pragma unroll
    for (int e = 0; e < KEXP; e++) acc[e] = 0.f;
    for (int d = tid; d < DDIM; d += 256) {
        float hv = hp[d];
        const float4* wr = reinterpret_cast<const float4*>(Wr + (size_t)d * KEXP);
        float4 w0 = wr[0], w1 = wr[1];
        acc[0] += hv * w0.x; acc[1] += hv * w0.y; acc[2] += hv * w0.z; acc[3] += hv * w0.w;
        acc[4] += hv * w1.x; acc[5] += hv * w1.y; acc[6] += hv * w1.z; acc[7] += hv * w1.w;
    }
#pragma unroll
    for (int off = 16; off > 0; off >>= 1)
#pragma unroll
        for (int e = 0; e < KEXP; e++)
            acc[e] += __shfl_down_sync(0xffffffffu, acc[e], off);

    __shared__ float ws[8][KEXP];
    const int w = tid >> 5, lane = tid & 31;
    if (lane == 0)
#pragma unroll
        for (int e = 0; e < KEXP; e++) ws[w][e] = acc[e];
    __syncthreads();
    if (tid == 0) {
        float l[KEXP];
#pragma unroll
        for (int e = 0; e < KEXP; e++) {
            float s = br[e];
#pragma unroll
            for (int ww = 0; ww < 8; ww++) s += ws[ww][e];
            l[e] = s;
        }
        float mx = l[0];
#pragma unroll
        for (int e = 1; e < KEXP; e++) mx = fmaxf(mx, l[e]);
        float sum = 0.f;
#pragma unroll
        for (int e = 0; e < KEXP; e++) { l[e] = expf(l[e] - mx); sum += l[e]; }
        float inv = 1.f / sum;
#pragma unroll
        for (int e = 0; e < KEXP; e++) gate[m * KEXP + e] = l[e] * inv;
    }
}

// ---------------------------------------------------------------------------
// per-mask pair scores + segment softmax (anchors u = m-5 .. m+4 in [0,UPOS))
// ---------------------------------------------------------------------------
__global__ void score_combine(const float* __restrict__ q, const float* __restrict__ k,
                              const float* __restrict__ bq, const float* __restrict__ bk,
                              float* __restrict__ cmb)
{
    const int m = blockIdx.x;
    const int w = threadIdx.x >> 5;    // 0..9
    const int lane = threadIdx.x & 31;
    const int u = m - 5 + w;
    const bool valid = (u >= 0) && (u < UPOS);

    __shared__ float sc[10];
    float s = 0.f;
    if (valid) {
        const float* qp = q + (size_t)m * DPROJ;
        const float* kp = k + (size_t)u * DPROJ;
        for (int i = lane; i < DPROJ; i += 32)
            s += (qp[i] + bq[i]) * (kp[i] + bk[i]);
#pragma unroll
        for (int off = 16; off > 0; off >>= 1)
            s += __shfl_down_sync(0xffffffffu, s, off);
    }
    if (lane == 0) sc[w] = valid ? s * 0.044194173824159216f : -1e30f;
    __syncthreads();
    if (threadIdx.x == 0) {
        float mx = -1e30f;
#pragma unroll
        for (int j = 0; j < 10; j++) mx = fmaxf(mx, sc[j]);
        float e[10]; float sum = 0.f;
#pragma unroll
        for (int j = 0; j < 10; j++) {
            e[j] = (sc[j] > -1e29f) ? expf(sc[j] - mx) : 0.f;
            sum += e[j];
        }
        float inv = 1.f / fmaxf(sum, 1e-8f);
#pragma unroll
        for (int j = 0; j < 10; j++) cmb[m * 10 + j] = e[j] * inv;
    }
}

// ---------------------------------------------------------------------------
// g_G[m, n] = tf32( gate[m][n/H] * sum_j cmb[m][j] * gelu(A[u_j,n]+B[m,n]+b1[n]) )
// ---------------------------------------------------------------------------
__global__ void aggregate_kernel(const float* __restrict__ A, const float* __restrict__ B,
                                 const float* __restrict__ b1, const float* __restrict__ cmb,
                                 const float* __restrict__ gate, uint32_t* __restrict__ G)
{
    const int m = blockIdx.y;
    const int n = blockIdx.x * 256 + threadIdx.x;
    __shared__ float c[10];
    __shared__ int   us[10];
    __shared__ float gt[KEXP];
    if (threadIdx.x < 10) {
        c[threadIdx.x] = cmb[m * 10 + threadIdx.x];
        int u = m - 5 + threadIdx.x;
        us[threadIdx.x] = min(max(u, 0), UPOS - 1);
    }
    if (threadIdx.x < KEXP) gt[threadIdx.x] = gate[m * KEXP + threadIdx.x];
    __syncthreads();

    const float Bv = B[(size_t)m * EHDIM + n] + b1[n];
    float acc = 0.f;
#pragma unroll
    for (int j = 0; j < 10; j++) {
        float x = A[(size_t)us[j] * EHDIM + n] + Bv;
        float ge = 0.5f * x * (1.f + erff(x * 0.70710678118654752f));
        acc = fmaf(c[j], ge, acc);
    }
    G[(size_t)m * EHDIM + n] = f2tf(gt[n >> 11] * acc);
}

// out[midx[m], d] += sum_e gate[m][e] * b2[e][d]
__global__ void addb2_kernel(const float* __restrict__ gate, const float* __restrict__ b2,
                             const int* __restrict__ midx, float* __restrict__ out)
{
    const int m = blockIdx.y;
    const int d = blockIdx.x * 256 + threadIdx.x;
    float s = 0.f;
#pragma unroll
    for (int e = 0; e < KEXP; e++)
        s = fmaf(gate[m * KEXP + e], b2[(size_t)e * DDIM + d], s);
    out[(size_t)midx[m] * DDIM + d] += s;
}

// ---------------------------------------------------------------------------
extern "C" void kernel_launch(void* const* d_in, const int* in_sizes, int n_in,
                              void* d_out, int out_size)
{
    const float* h   = (const float*)d_in[0];
    const int*   midx= (const int*)d_in[1];
    const int*   uidx= (const int*)d_in[2];
    const float* Wr  = (const float*)d_in[4];
    const float* br  = (const float*)d_in[5];
    const float* W1  = (const float*)d_in[6];
    const float* b1  = (const float*)d_in[7];
    const float* W2  = (const float*)d_in[8];
    const float* b2  = (const float*)d_in[9];
    const float* Wq  = (const float*)d_in[10];
    const float* bq  = (const float*)d_in[11];
    const float* Wk  = (const float*)d_in[12];
    const float* bk  = (const float*)d_in[13];
    float* out = (float*)d_out;

    float *pA, *pB, *pq, *pk, *pgate, *pcmb;
    uint32_t *pG, *phM, *phU;
    cudaGetSymbolAddress((void**)&pA, g_A);
    cudaGetSymbolAddress((void**)&pB, g_B);
    cudaGetSymbolAddress((void**)&pG, g_G);
    cudaGetSymbolAddress((void**)&phM, g_hM);
    cudaGetSymbolAddress((void**)&phU, g_hU);
    cudaGetSymbolAddress((void**)&pq, g_q);
    cudaGetSymbolAddress((void**)&pk, g_k);
    cudaGetSymbolAddress((void**)&pgate, g_gate);
    cudaGetSymbolAddress((void**)&pcmb, g_cmb);

    cudaFuncSetAttribute(gemm_cp, cudaFuncAttributeMaxDynamicSharedMemorySize, SM_TOTAL);

    // zero output (odd rows stay zero; even rows overwritten by final GEMM)
    cudaMemsetAsync(out, 0, (size_t)out_size * sizeof(float));

    // gather + convert h rows (A operands; weights stay raw fp32)
    gather_tf32<<<MPOS, 256>>>(h, midx, phM);
    gather_tf32<<<UPOS, 256>>>(h, uidx, phU);

    // gate (fp32)
    gate_kernel<<<MPOS, 256>>>(h, midx, Wr, br, pgate);

    // q = hM @ Wq ; k = hU @ Wk  (batched via blockIdx.z)
    gemm_cp<<<dim3(MPOS / 128, DPROJ / 128, 2), 128, SM_TOTAL>>>(
        phM, DDIM, Wq, DPROJ, DPROJ, 0, pq, DPROJ, nullptr, DDIM,
        phU, Wk, pk);

    // per-mask segment softmax over <=10 anchors
    score_combine<<<MPOS, 320>>>(pq, pk, bq, bk, pcmb);

    // A = hU @ W1_top ; B = hM @ W1_bot — ONE launch via blockIdx.z
    gemm_cp<<<dim3(UPOS / 128, EHDIM / 128, 2), 128, SM_TOTAL>>>(
        phU, DDIM, W1, HHID, HHID, (size_t)2 * DDIM * HHID, pA, EHDIM, nullptr, DDIM,
        phM, W1 + (size_t)DDIM * HHID, pB);

    // gelu + combine aggregation, gate folded in, tf32 output
    aggregate_kernel<<<dim3(EHDIM / 256, MPOS), 256>>>(pA, pB, b1, pcmb, pgate, pG);

    // out[masks] = G @ W2_flat   (K = 16384, W2 flat contiguous [16384 x 4096])
    gemm_cp<<<dim3(MPOS / 128, DDIM / 128, 1), 128, SM_TOTAL>>>(
        pG, EHDIM, W2, DDIM, DDIM, 0, out, DDIM, midx, EHDIM,
        nullptr, nullptr, nullptr);

    // + sum_e gate*b2 (combine weights sum to 1 per mask)
    addb2_kernel<<<dim3(DDIM / 256, MPOS), 256>>>(pgate, b2, midx, out);
}